// round 3
// baseline (speedup 1.0000x reference)
#include <cuda_runtime.h>
#include <cstdint>

// ---------------- SLAYER constants (double -> f32) --------------------------------
#define C2A 1.8096748360719190f   // 2*exp(-0.1)
#define CA2 0.8187307530779818f   // exp(-0.2)
#define CB1 0.2459603111156949f   // e*exp(-0.1)/10

// ---------------- scratch (static device memory; no allocation) -------------------
#define UMAX 52428800  // 100*4*32*64*64 floats
__device__ float g_u[UMAX];
__device__ unsigned char g_s8a[13107200];
__device__ unsigned char g_s8b[13107200];
__device__ float g_part[4 * 400 * 512];

// ---------------- f32x2 helpers ---------------------------------------------------
__device__ __forceinline__ unsigned long long pk2(float a, float b) {
    unsigned long long r;
    asm("mov.b64 %0, {%1,%2};" : "=l"(r) : "f"(a), "f"(b));
    return r;
}
__device__ __forceinline__ unsigned long long fma2(unsigned long long a,
                                                   unsigned long long b,
                                                   unsigned long long c) {
    unsigned long long d;
    asm("fma.rn.f32x2 %0, %1, %2, %3;" : "=l"(d) : "l"(a), "l"(b), "l"(c));
    return d;
}
__device__ __forceinline__ float2 upk(unsigned long long v) {
    float2 r;
    asm("mov.b64 {%0,%1}, %2;" : "=f"(r.x), "=f"(r.y) : "l"(v));
    return r;
}

// ---------------- SP0: pool(2x2)*11 on raw input ([B,C,128,128,T]) + scan ---------
__global__ void scan_in_k(const float* __restrict__ sin, unsigned char* __restrict__ sout) {
    const int N = 32768;  // 4*2*64*64
    int n = blockIdx.x * blockDim.x + threadIdx.x;
    if (n >= N) return;
    int w = n & 63, h = (n >> 6) & 63, c = (n >> 12) & 1, b = n >> 13;
    const float* p0 = sin + ((size_t)((b * 2 + c) * 128 + 2 * h) * 128 + 2 * w) * 100;
    const float* p1 = p0 + 100;
    const float* p2 = p0 + 12800;
    const float* p3 = p2 + 100;
    float a1 = 0.f, a2 = 0.f, cp = 0.f, r1 = 0.f, r2 = 0.f, sp = 0.f;
    for (int t = 0; t < 100; t++) {
        float xv = 11.0f * (p0[t] + p1[t] + p2[t] + p3[t]);
        float uu = C2A * a1 - CA2 * a2 + CB1 * cp;
        float yy = C2A * r1 - CA2 * r2 + CB1 * sp;
        float ss = (uu - 20.0f * yy >= 10.0f) ? 1.0f : 0.0f;
        sout[(size_t)t * N + n] = (unsigned char)ss;
        a2 = a1; a1 = uu; cp = xv;
        r2 = r1; r1 = yy; sp = ss;
    }
}

// ---------------- fused: conv-neuron scan (2x2 group) + pool + pooled-neuron scan --
template <int C, int H, int W>
__global__ void scanpool_k(const float* __restrict__ u, unsigned char* __restrict__ s) {
    constexpr int N = 4 * C * H * W;
    int n = blockIdx.x * blockDim.x + threadIdx.x;
    if (n >= N) return;
    int w = n % W, h = (n / W) % H, c = (n / (W * H)) % C, b = n / (W * H * C);
    const float* base = u + (size_t)(((b * C + c) * (2 * H) + 2 * h) * (2 * W) + 2 * w);
    constexpr size_t ST = (size_t)16 * C * H * W;  // per-t stride (4 images)
    float y1[4], y2[4], xp[4], r1[4], r2[4], sp[4];
#pragma unroll
    for (int i = 0; i < 4; i++) { y1[i] = y2[i] = xp[i] = r1[i] = r2[i] = sp[i] = 0.f; }
    float py1 = 0.f, py2 = 0.f, pxp = 0.f, pr1 = 0.f, pr2 = 0.f, psp = 0.f;
    for (int t = 0; t < 100; t++) {
        float2 ra = *(const float2*)(base);
        float2 rb = *(const float2*)(base + 2 * W);
        float xin[4] = {ra.x, ra.y, rb.x, rb.y};
        float ssum = 0.f;
#pragma unroll
        for (int i = 0; i < 4; i++) {
            float yy = C2A * y1[i] - CA2 * y2[i] + CB1 * xp[i];
            float rr = C2A * r1[i] - CA2 * r2[i] + CB1 * sp[i];
            float si = (yy - 20.0f * rr >= 10.0f) ? 1.0f : 0.0f;
            y2[i] = y1[i]; y1[i] = yy; xp[i] = xin[i];
            r2[i] = r1[i]; r1[i] = rr; sp[i] = si;
            ssum += si;
        }
        float pu = C2A * py1 - CA2 * py2 + CB1 * pxp;
        float pr = C2A * pr1 - CA2 * pr2 + CB1 * psp;
        float ps = (pu - 20.0f * pr >= 10.0f) ? 1.0f : 0.0f;
        py2 = py1; py1 = pu; pxp = 11.0f * ssum;
        pr2 = pr1; pr1 = pr; psp = ps;
        s[(size_t)t * N + n] = (unsigned char)ps;
        base += ST;
    }
}

// ---------------- plain psp+spike scan (fp32 u -> u8 spikes) -----------------------
__global__ void scan_k(const float* __restrict__ u, unsigned char* __restrict__ s, int N) {
    int n = blockIdx.x * blockDim.x + threadIdx.x;
    if (n >= N) return;
    float p1 = 0.f, p2 = 0.f, cp = 0.f, r1 = 0.f, r2 = 0.f, sp = 0.f;
    for (int t = 0; t < 100; t++) {
        float c  = u[(size_t)t * N + n];
        float uu = C2A * p1 - CA2 * p2 + CB1 * cp;
        float yy = C2A * r1 - CA2 * r2 + CB1 * sp;
        float ss = (uu - 20.0f * yy >= 10.0f) ? 1.0f : 0.0f;
        s[(size_t)t * N + n] = (unsigned char)ss;
        p2 = p1; p1 = uu; cp = c;
        r2 = r1; r1 = yy; sp = ss;
    }
}

// ---------------- direct conv, u8 spikes in, fp32 u out, f32x2 FFMA ----------------
// thread tile: 4 pixels (1 row, cols strided by TPX) x 16 out-channels (8 f32x2).
// block: TPX*TY pixel-slots x OCG oc-groups = 256 threads, __launch_bounds__(256,2).
template <int IC, int OC, int HH, int WW, int K, int ICB, int TPX, int TY, int OCG, int XST>
__global__ void __launch_bounds__(256, 2)
conv_k(const unsigned char* __restrict__ x, const float* __restrict__ wt,
       float* __restrict__ y) {
    constexpr int TX = TPX * 4, PAD = K / 2, PS = TPX * TY, NT = PS * OCG;
    constexpr int SW = TX + K - 1, SH = TY + K - 1;
    __shared__ __align__(16) float xs[ICB * SH * XST];
    __shared__ __align__(16) float ws[ICB * K * K * OCG * 16];
    const int tid = threadIdx.x;
    const int ps = tid % PS, oslot = tid / PS;
    const int tx = ps % TPX, ty = ps / TPX;
    constexpr int tilesx = WW / TX;
    const int tx0 = (blockIdx.x % tilesx) * TX, ty0 = (blockIdx.x / tilesx) * TY;
    const int ocg0 = blockIdx.y * (OCG * 16);
    const unsigned char* xb = x + (size_t)blockIdx.z * IC * HH * WW;

    unsigned long long acc[4][8];
#pragma unroll
    for (int c = 0; c < 4; c++)
#pragma unroll
        for (int o = 0; o < 8; o++) acc[c][o] = 0ULL;

    for (int icc = 0; icc < IC; icc += ICB) {
        // stage input tile (u8 -> f32)
        for (int idx = tid; idx < ICB * SH * SW; idx += NT) {
            int ic = idx / (SH * SW);
            int r = idx - ic * SH * SW;
            int yy = r / SW, xx = r - yy * SW;
            int gy = ty0 + yy - PAD, gx = tx0 + xx - PAD;
            float v = 0.f;
            if (gy >= 0 && gy < HH && gx >= 0 && gx < WW)
                v = (float)xb[(size_t)(icc + ic) * HH * WW + gy * WW + gx];
            xs[(ic * SH + yy) * XST + xx] = v;
        }
        // stage weights: layout [ic][kk][g][o], 16 floats contiguous per (ic,kk,g)
        for (int idx = tid; idx < ICB * K * K * OCG * 16; idx += NT) {
            int o = idx & 15;
            int r = idx >> 4;
            int g = r % OCG;
            int r2 = r / OCG;
            int kk = r2 % (K * K);
            int ic = r2 / (K * K);
            ws[idx] = wt[((size_t)(ocg0 + g * 16 + o) * IC + icc + ic) * (K * K) + kk];
        }
        __syncthreads();
#pragma unroll 2
        for (int ic = 0; ic < ICB; ic++) {
#pragma unroll
            for (int kh = 0; kh < K; kh++) {
#pragma unroll
                for (int kw = 0; kw < K; kw++) {
                    unsigned long long xp[4];
#pragma unroll
                    for (int c = 0; c < 4; c++) {
                        float v = xs[(ic * SH + ty + kh) * XST + tx + c * TPX + kw];
                        xp[c] = pk2(v, v);
                    }
                    const ulonglong2* wq = reinterpret_cast<const ulonglong2*>(
                        &ws[((ic * K * K + kh * K + kw) * OCG + oslot) * 16]);
                    ulonglong2 w01 = wq[0], w23 = wq[1], w45 = wq[2], w67 = wq[3];
                    unsigned long long wr[8] = {w01.x, w01.y, w23.x, w23.y,
                                                w45.x, w45.y, w67.x, w67.y};
#pragma unroll
                    for (int c = 0; c < 4; c++)
#pragma unroll
                        for (int o = 0; o < 8; o++)
                            acc[c][o] = fma2(xp[c], wr[o], acc[c][o]);
                }
            }
        }
        __syncthreads();
    }
    float* yb = y + ((size_t)blockIdx.z * OC + ocg0 + oslot * 16) * HH * WW;
    const int row = ty0 + ty;
#pragma unroll
    for (int c = 0; c < 4; c++) {
        int col = tx0 + tx + c * TPX;
#pragma unroll
        for (int o = 0; o < 8; o++) {
            float2 v = upk(acc[c][o]);
            yb[(size_t)(2 * o) * HH * WW + (size_t)row * WW + col] = v.x;
            yb[(size_t)(2 * o + 1) * HH * WW + (size_t)row * WW + col] = v.y;
        }
    }
}

// ---------------- SF4a GEMM: [400 x 8192](u8) * [8192 -> 512], split-K=4 ----------
__global__ void __launch_bounds__(256)
gemm4a_k(const unsigned char* __restrict__ x, const float* __restrict__ w,
         float* __restrict__ part) {
    __shared__ __align__(16) float xs[16][64];
    __shared__ __align__(16) float ws[16][64];
    const int tid = threadIdx.x;
    const int tm = tid % 16, tn = tid / 16;
    const int bm0 = blockIdx.x * 64, bn0 = blockIdx.y * 64;
    const int k0b = blockIdx.z * 2048;
    unsigned long long acc[4][2];
#pragma unroll
    for (int i = 0; i < 4; i++) { acc[i][0] = 0ULL; acc[i][1] = 0ULL; }
    const int lrow = tid >> 2, lc4 = (tid & 3) * 4;

    for (int k0 = k0b; k0 < k0b + 2048; k0 += 16) {
        int m = bm0 + lrow;
        uchar4 xv = make_uchar4(0, 0, 0, 0);
        if (m < 400) xv = *reinterpret_cast<const uchar4*>(x + (size_t)m * 8192 + k0 + lc4);
        xs[lc4 + 0][lrow] = (float)xv.x; xs[lc4 + 1][lrow] = (float)xv.y;
        xs[lc4 + 2][lrow] = (float)xv.z; xs[lc4 + 3][lrow] = (float)xv.w;
        float4 wv = *reinterpret_cast<const float4*>(w + (size_t)(bn0 + lrow) * 8192 + k0 + lc4);
        ws[lc4 + 0][lrow] = wv.x; ws[lc4 + 1][lrow] = wv.y;
        ws[lc4 + 2][lrow] = wv.z; ws[lc4 + 3][lrow] = wv.w;
        __syncthreads();
#pragma unroll
        for (int kk = 0; kk < 16; kk++) {
            float4 a = *reinterpret_cast<const float4*>(&xs[kk][tm * 4]);
            const unsigned long long* wp =
                reinterpret_cast<const unsigned long long*>(&ws[kk][tn * 4]);
            unsigned long long w0 = wp[0], w1 = wp[1];
            unsigned long long a0 = pk2(a.x, a.x), a1 = pk2(a.y, a.y);
            unsigned long long a2 = pk2(a.z, a.z), a3 = pk2(a.w, a.w);
            acc[0][0] = fma2(a0, w0, acc[0][0]); acc[0][1] = fma2(a0, w1, acc[0][1]);
            acc[1][0] = fma2(a1, w0, acc[1][0]); acc[1][1] = fma2(a1, w1, acc[1][1]);
            acc[2][0] = fma2(a2, w0, acc[2][0]); acc[2][1] = fma2(a2, w1, acc[2][1]);
            acc[3][0] = fma2(a3, w0, acc[3][0]); acc[3][1] = fma2(a3, w1, acc[3][1]);
        }
        __syncthreads();
    }
    float* pb = part + (size_t)blockIdx.z * 204800;
#pragma unroll
    for (int i = 0; i < 4; i++) {
        int m = bm0 + tm * 4 + i;
        if (m < 400) {
            float2 v0 = upk(acc[i][0]), v1 = upk(acc[i][1]);
            float4 v = make_float4(v0.x, v0.y, v1.x, v1.y);
            *reinterpret_cast<float4*>(pb + (size_t)m * 512 + bn0 + tn * 4) = v;
        }
    }
}

__global__ void reduce4_k(const float* __restrict__ part, float* __restrict__ u) {
    int i = blockIdx.x * blockDim.x + threadIdx.x;
    if (i < 204800)
        u[i] = ((part[i] + part[204800 + i]) + part[409600 + i]) + part[614400 + i];
}

// ---------------- SF4b GEMM: [400 x 512](u8) * [512 -> 11] -------------------------
__global__ void gemm4b_k(const unsigned char* __restrict__ x, const float* __restrict__ w,
                         float* __restrict__ u) {
    int tb = blockIdx.x;
    int wid = threadIdx.x >> 5, lid = threadIdx.x & 31;  // 11 warps
    const unsigned char* xr = x + (size_t)tb * 512;
    const float* wr = w + (size_t)wid * 512;
    float s = 0.f;
    for (int k = lid; k < 512; k += 32) s += (float)xr[k] * wr[k];
#pragma unroll
    for (int off = 16; off; off >>= 1) s += __shfl_xor_sync(0xffffffffu, s, off);
    if (lid == 0) u[tb * 11 + wid] = s;
}

// ---------------- final scan: u4b [t][b*11+o] -> d_out [b][11][t] ------------------
__global__ void scan_out_k(const float* __restrict__ u, float* __restrict__ out) {
    int n = threadIdx.x;
    if (n >= 44) return;
    int b = n / 11, o = n % 11;
    float a1 = 0.f, a2 = 0.f, cp = 0.f, r1 = 0.f, r2 = 0.f, sp = 0.f;
    for (int t = 0; t < 100; t++) {
        float c  = u[t * 44 + n];
        float uu = C2A * a1 - CA2 * a2 + CB1 * cp;
        float yy = C2A * r1 - CA2 * r2 + CB1 * sp;
        float ss = (uu - 20.0f * yy >= 10.0f) ? 1.0f : 0.0f;
        out[(b * 11 + o) * 100 + t] = ss;
        a2 = a1; a1 = uu; cp = c;
        r2 = r1; r1 = yy; sp = ss;
    }
}

// ---------------- driver ----------------------------------------------------------
extern "C" void kernel_launch(void* const* d_in, const int* in_sizes, int n_in,
                              void* d_out, int out_size) {
    const float* s_in = (const float*)d_in[0];
    const float* w1   = (const float*)d_in[1];
    const float* w2   = (const float*)d_in[2];
    const float* w3   = (const float*)d_in[3];
    const float* wf4a = (const float*)d_in[4];
    const float* wf4b = (const float*)d_in[5];
    float* out = (float*)d_out;

    float *u, *pp;
    unsigned char *sa, *sb;
    cudaGetSymbolAddress((void**)&u, g_u);
    cudaGetSymbolAddress((void**)&sa, g_s8a);
    cudaGetSymbolAddress((void**)&sb, g_s8b);
    cudaGetSymbolAddress((void**)&pp, g_part);

    // SP0: pool raw input + scan -> sa : [t][b][2][64][64] u8
    scan_in_k<<<128, 256>>>(s_in, sa);
    // SC1: conv 5x5 -> u : [z][32][64][64]   (TPX=16,TY=16,OCG=1, XST=80)
    conv_k<2, 32, 64, 64, 5, 2, 16, 16, 1, 80><<<dim3(4, 2, 400), 256>>>(sa, w1, u);
    // SC1 scan + SP1 pool + scan -> sb : [t][b][32][32][32] u8
    scanpool_k<32, 32, 32><<<512, 256>>>(u, sb);
    // SC2: conv 3x3 -> u : [z][64][32][32]   (TPX=8,TY=32,OCG=1, XST=40)
    conv_k<32, 64, 32, 32, 3, 4, 8, 32, 1, 40><<<dim3(1, 4, 400), 256>>>(sb, w2, u);
    // scan + SP2 -> sa : [t][b][64][16][16] u8
    scanpool_k<64, 16, 16><<<256, 256>>>(u, sa);
    // SC3: conv 3x3 -> u : [z][128][16][16]  (TPX=4,TY=16,OCG=4, XST=20)
    conv_k<64, 128, 16, 16, 3, 8, 4, 16, 4, 20><<<dim3(1, 2, 400), 256>>>(sa, w3, u);
    // scan + SP3 -> sb : [t][b][128][8][8] = [t][b][8192] u8
    scanpool_k<128, 8, 8><<<128, 256>>>(u, sb);
    // SF4a: GEMM split-K + reduce -> u : [z][512]; scan -> sa
    gemm4a_k<<<dim3(7, 8, 4), 256>>>(sb, wf4a, pp);
    reduce4_k<<<800, 256>>>(pp, u);
    scan_k<<<8, 256>>>(u, sa, 2048);
    // SF4b: GEMM -> u : [z][11]; final scan -> d_out [4][11][100]
    gemm4b_k<<<400, 352>>>(sa, wf4b, u);
    scan_out_k<<<1, 64>>>(u, out);
}

// round 4
// speedup vs baseline: 1.7751x; 1.7751x over previous
#include <cuda_runtime.h>
#include <cuda_bf16.h>
#include <cstdint>

// ---------------- SLAYER constants (double -> f32) --------------------------------
#define C2A 1.8096748360719190f   // 2*exp(-0.1)
#define CA2 0.8187307530779818f   // exp(-0.2)
#define CB1 0.2459603111156949f   // e*exp(-0.1)/10

// ---------------- scratch (static device memory; no allocation) -------------------
#define UMAX 52428800  // 100*4*32*64*64 floats
__device__ float g_u[UMAX];
__device__ unsigned char g_s8a[13107200];
__device__ unsigned char g_s8b[13107200];
__device__ float g_part[4 * 400 * 512];
__device__ float g_wp[512 * 8192];       // permuted SF4a weights
__device__ uint2 g_B1[5 * 4 * 3 * 32];       // SC1 frag weights
__device__ uint2 g_B2[18 * 8 * 3 * 32];      // SC2 frag weights
__device__ uint2 g_B3[36 * 16 * 3 * 32];     // SC3 frag weights

// ---------------- f32x2 helpers (gemm4a) ------------------------------------------
__device__ __forceinline__ unsigned long long pk2(float a, float b) {
    unsigned long long r;
    asm("mov.b64 %0, {%1,%2};" : "=l"(r) : "f"(a), "f"(b));
    return r;
}
__device__ __forceinline__ unsigned long long fma2(unsigned long long a,
                                                   unsigned long long b,
                                                   unsigned long long c) {
    unsigned long long d;
    asm("fma.rn.f32x2 %0, %1, %2, %3;" : "=l"(d) : "l"(a), "l"(b), "l"(c));
    return d;
}
__device__ __forceinline__ float2 upk(unsigned long long v) {
    float2 r;
    asm("mov.b64 {%0,%1}, %2;" : "=f"(r.x), "=f"(r.y) : "l"(v));
    return r;
}

// ---------------- mma / ldmatrix helpers ------------------------------------------
__device__ __forceinline__ void mmab(float (&c)[4], uint32_t a0, uint32_t a1,
                                     uint32_t a2, uint32_t a3, uint32_t b0, uint32_t b1) {
    asm volatile(
        "mma.sync.aligned.m16n8k16.row.col.f32.bf16.bf16.f32 "
        "{%0,%1,%2,%3}, {%4,%5,%6,%7}, {%8,%9}, {%0,%1,%2,%3};"
        : "+f"(c[0]), "+f"(c[1]), "+f"(c[2]), "+f"(c[3])
        : "r"(a0), "r"(a1), "r"(a2), "r"(a3), "r"(b0), "r"(b1));
}
__device__ __forceinline__ void ldm4(uint32_t (&a)[4], uint32_t addr) {
    asm volatile("ldmatrix.sync.aligned.m8n8.x4.shared.b16 {%0,%1,%2,%3}, [%4];"
                 : "=r"(a[0]), "=r"(a[1]), "=r"(a[2]), "=r"(a[3]) : "r"(addr));
}

// ---------------- weight 3-way bf16 split -----------------------------------------
__device__ __forceinline__ unsigned short wsplit(float w, int sp) {
    __nv_bfloat16 h = __float2bfloat16(w);
    if (sp == 0) return __bfloat16_as_ushort(h);
    float r = w - __bfloat162float(h);
    __nv_bfloat16 m = __float2bfloat16(r);
    if (sp == 1) return __bfloat16_as_ushort(m);
    float r2 = r - __bfloat162float(m);
    return __bfloat16_as_ushort(__float2bfloat16(r2));
}

// ---------------- prep: SC1 frag weights (k = kw*2+ic, kw>=5 zero) ----------------
__global__ void prepB1_k(const float* __restrict__ wt, uint2* __restrict__ B) {
    int idx = blockIdx.x * blockDim.x + threadIdx.x;
    if (idx >= 5 * 4 * 3 * 32) return;
    int lane = idx & 31;
    int r = idx >> 5;
    int sp = r % 3; r /= 3;
    int nt = r & 3;
    int kh = r >> 2;
    int g = lane >> 2, tg = lane & 3;
    int oc = nt * 8 + g;
    unsigned short v[4];
#pragma unroll
    for (int i = 0; i < 4; i++) {
        int k = tg * 2 + (i & 1) + (i >> 1) * 8;
        int kw = k >> 1, ic = k & 1;
        float w = (kw < 5) ? wt[((oc * 2 + ic) * 5 + kh) * 5 + kw] : 0.f;
        v[i] = wsplit(w, sp);
    }
    B[idx] = make_uint2((unsigned)v[0] | ((unsigned)v[1] << 16),
                        (unsigned)v[2] | ((unsigned)v[3] << 16));
}

// ---------------- prep: 3x3 conv frag weights -------------------------------------
template <int IC, int NTG, int NICB>
__global__ void prepB3_k(const float* __restrict__ wt, uint2* __restrict__ B, int total) {
    int idx = blockIdx.x * blockDim.x + threadIdx.x;
    if (idx >= total) return;
    int lane = idx & 31;
    int r = idx >> 5;
    int sp = r % 3; r /= 3;
    int ntg = r % NTG;
    int it = r / NTG;
    int icb = it % NICB;
    int tap = it / NICB;
    int kh = tap / 3, kw = tap % 3;
    int g = lane >> 2, tg = lane & 3;
    int oc = ntg * 8 + g;
    unsigned short v[4];
#pragma unroll
    for (int i = 0; i < 4; i++) {
        int k = tg * 2 + (i & 1) + (i >> 1) * 8;
        int ic = icb * 16 + k;
        v[i] = wsplit(wt[((oc * IC + ic) * 3 + kh) * 3 + kw], sp);
    }
    B[idx] = make_uint2((unsigned)v[0] | ((unsigned)v[1] << 16),
                        (unsigned)v[2] | ((unsigned)v[3] << 16));
}

// ---------------- prep: permute SF4a weights (c,y,x) -> (y,x,c) -------------------
__global__ void permw_k(const float* __restrict__ w, float* __restrict__ wp) {
    int idx = blockIdx.x * blockDim.x + threadIdx.x;
    if (idx >= 512 * 8192) return;
    int o = idx >> 13, r = idx & 8191;
    int y = r >> 10, x = (r >> 7) & 7, c = r & 127;
    wp[idx] = w[(o << 13) + ((c * 8 + y) * 8 + x)];
}

// ---------------- SP0: pool(2x2)*11 on raw input + scan -> channel-last u8 --------
__global__ void scan_in_k(const float* __restrict__ sin, unsigned char* __restrict__ sout) {
    const int N = 32768;  // 4 b * 64 * 64 * 2 c
    int n = blockIdx.x * blockDim.x + threadIdx.x;
    if (n >= N) return;
    int c = n & 1, x = (n >> 1) & 63, y = (n >> 7) & 63, b = n >> 13;
    const float* p0 = sin + ((size_t)((b * 2 + c) * 128 + 2 * y) * 128 + 2 * x) * 100;
    const float* p1 = p0 + 100;
    const float* p2 = p0 + 12800;
    const float* p3 = p2 + 100;
    float a1 = 0.f, a2 = 0.f, cp = 0.f, r1 = 0.f, r2 = 0.f, sp = 0.f;
    for (int t = 0; t < 100; t++) {
        float xv = 11.0f * (p0[t] + p1[t] + p2[t] + p3[t]);
        float uu = C2A * a1 - CA2 * a2 + CB1 * cp;
        float yy = C2A * r1 - CA2 * r2 + CB1 * sp;
        float ss = (uu - 20.0f * yy >= 10.0f) ? 1.0f : 0.0f;
        sout[(size_t)t * N + n] = (unsigned char)ss;
        a2 = a1; a1 = uu; cp = xv;
        r2 = r1; r1 = yy; sp = ss;
    }
}

// ---------------- fused conv-scan + pool + pooled-scan (channel-last) -------------
// u: [z][2h][2w][C] f32 ; out: [t][b][h][w][C] u8
template <int C, int H, int W>
__global__ void scanpool_k(const float* __restrict__ u, unsigned char* __restrict__ s) {
    constexpr int N = 4 * C * H * W;
    int n = blockIdx.x * blockDim.x + threadIdx.x;
    if (n >= N) return;
    int c = n % C;
    int r = n / C;
    int w = r % W, h = (r / W) % H, b = r / (W * H);
    const float* base = u + (size_t)b * 4 * H * W * C + ((size_t)(2 * h) * (2 * W) + 2 * w) * C + c;
    constexpr size_t ZST = (size_t)16 * H * W * C;  // per-t stride (4 images)
    float y1[4], y2[4], xp[4], r1[4], r2[4], sp[4];
#pragma unroll
    for (int i = 0; i < 4; i++) { y1[i] = y2[i] = xp[i] = r1[i] = r2[i] = sp[i] = 0.f; }
    float py1 = 0.f, py2 = 0.f, pxp = 0.f, pr1 = 0.f, pr2 = 0.f, psp = 0.f;
    for (int t = 0; t < 100; t++) {
        float xin[4];
        xin[0] = base[0];
        xin[1] = base[C];
        xin[2] = base[2 * W * C];
        xin[3] = base[(2 * W + 1) * C];
        float ssum = 0.f;
#pragma unroll
        for (int i = 0; i < 4; i++) {
            float yy = C2A * y1[i] - CA2 * y2[i] + CB1 * xp[i];
            float rr = C2A * r1[i] - CA2 * r2[i] + CB1 * sp[i];
            float si = (yy - 20.0f * rr >= 10.0f) ? 1.0f : 0.0f;
            y2[i] = y1[i]; y1[i] = yy; xp[i] = xin[i];
            r2[i] = r1[i]; r1[i] = rr; sp[i] = si;
            ssum += si;
        }
        float pu = C2A * py1 - CA2 * py2 + CB1 * pxp;
        float pr = C2A * pr1 - CA2 * pr2 + CB1 * psp;
        float ps = (pu - 20.0f * pr >= 10.0f) ? 1.0f : 0.0f;
        py2 = py1; py1 = pu; pxp = 11.0f * ssum;
        pr2 = pr1; pr1 = pr; psp = ps;
        s[(size_t)t * N + n] = (unsigned char)ps;
        base += ZST;
    }
}

// ---------------- plain psp+spike scan (fp32 u -> u8 spikes) -----------------------
__global__ void scan_k(const float* __restrict__ u, unsigned char* __restrict__ s, int N) {
    int n = blockIdx.x * blockDim.x + threadIdx.x;
    if (n >= N) return;
    float p1 = 0.f, p2 = 0.f, cp = 0.f, r1 = 0.f, r2 = 0.f, sp = 0.f;
    for (int t = 0; t < 100; t++) {
        float c = u[(size_t)t * N + n];
        float uu = C2A * p1 - CA2 * p2 + CB1 * cp;
        float yy = C2A * r1 - CA2 * r2 + CB1 * sp;
        float ss = (uu - 20.0f * yy >= 10.0f) ? 1.0f : 0.0f;
        s[(size_t)t * N + n] = (unsigned char)ss;
        p2 = p1; p1 = uu; cp = c;
        r2 = r1; r1 = yy; sp = ss;
    }
}

// ---------------- SC1: 5x5 conv, IC=2, OC=32, 64x64, tensor-core ------------------
// k = kw*2+ic (16 = 8kw x 2ic, kw>=5 weights zero), iters over kh (5).
// block: 8 warps x (M=64 px, N=32 oc). 8 image rows per block.
__global__ void __launch_bounds__(256)
conv1_k(const unsigned char* __restrict__ x, const uint2* __restrict__ B,
        float* __restrict__ u) {
    __shared__ __align__(16) __nv_bfloat16 xs[12 * 148];
    const int tid = threadIdx.x, lane = tid & 31, warp = tid >> 5;
    const int z = blockIdx.y, R0 = blockIdx.x * 8;
    const unsigned char* xb = x + (size_t)z * 8192;  // 64*64*2
    for (int idx = tid; idx < 12 * 72; idx += 256) {
        int sy = idx / 72, ix = idx % 72;
        int gy = R0 + sy - 2, gx = ix - 2;
        unsigned v0 = 0, v1 = 0;
        if (gy >= 0 && gy < 64 && gx >= 0 && gx < 64) {
            const unsigned char* p = xb + ((size_t)gy * 64 + gx) * 2;
            v0 = p[0]; v1 = p[1];
        }
        unsigned pack = (v0 ? 0x3F80u : 0u) | (v1 ? 0x3F800000u : 0u);
        *(unsigned*)&xs[sy * 148 + ix * 2] = pack;
    }
    __syncthreads();
    const int g = lane >> 2, tg = lane & 3;
    float acc[4][4][4];
#pragma unroll
    for (int mt = 0; mt < 4; mt++)
#pragma unroll
        for (int nt = 0; nt < 4; nt++)
#pragma unroll
            for (int i = 0; i < 4; i++) acc[mt][nt][i] = 0.f;
    int lyA[4], lxA[4];
#pragma unroll
    for (int mt = 0; mt < 4; mt++) {
        int p = warp * 64 + mt * 16 + g;
        lyA[mt] = p >> 6;
        lxA[mt] = p & 63;
    }
#pragma unroll
    for (int kh = 0; kh < 5; kh++) {
        uint32_t a[4][4];
#pragma unroll
        for (int mt = 0; mt < 4; mt++) {
            int rb = (lyA[mt] + kh) * 148;
            a[mt][0] = *(const unsigned*)&xs[rb + (lxA[mt] + tg) * 2];
            a[mt][1] = *(const unsigned*)&xs[rb + (lxA[mt] + 8 + tg) * 2];
            a[mt][2] = *(const unsigned*)&xs[rb + (lxA[mt] + tg + 4) * 2];
            a[mt][3] = *(const unsigned*)&xs[rb + (lxA[mt] + 8 + tg + 4) * 2];
        }
#pragma unroll
        for (int nt = 0; nt < 4; nt++)
#pragma unroll
            for (int sp = 0; sp < 3; sp++) {
                uint2 b = B[((kh * 4 + nt) * 3 + sp) * 32 + lane];
#pragma unroll
                for (int mt = 0; mt < 4; mt++)
                    mmab(acc[mt][nt], a[mt][0], a[mt][1], a[mt][2], a[mt][3], b.x, b.y);
            }
    }
    float* ui = u + (size_t)z * 4096 * 32;
#pragma unroll
    for (int mt = 0; mt < 4; mt++) {
        int p0 = R0 * 64 + warp * 64 + mt * 16 + g;
#pragma unroll
        for (int nt = 0; nt < 4; nt++) {
            int oc = nt * 8 + tg * 2;
            *(float2*)&ui[(size_t)p0 * 32 + oc] = make_float2(acc[mt][nt][0], acc[mt][nt][1]);
            *(float2*)&ui[(size_t)(p0 + 8) * 32 + oc] = make_float2(acc[mt][nt][2], acc[mt][nt][3]);
        }
    }
}

// ---------------- 3x3 convs (SC2/SC3), tensor-core implicit GEMM ------------------
// channel-last spikes in, channel-last f32 u out. 8 rows per block, 8 warps
// organized MG m-groups (64 px each) x NG n-groups (32 oc each).
template <int IC, int OC, int W, int MG, int NG>
__global__ void __launch_bounds__(256)
conv3_k(const unsigned char* __restrict__ x, const uint2* __restrict__ B,
        float* __restrict__ u) {
    constexpr int XP = IC + 8;          // bf16 pitch per x-position (16B-aligned step)
    constexpr int SXW = W + 2;
    constexpr int NICB = IC / 16, NTG = OC / 8;
    __shared__ __align__(16) __nv_bfloat16 xs[10 * SXW * XP];
    const int tid = threadIdx.x, lane = tid & 31, warp = tid >> 5;
    const int mg = warp % MG, ng = warp / MG;
    const int z = blockIdx.y, R0 = blockIdx.x * 8;
    const unsigned char* xb = x + (size_t)z * W * W * IC;
    for (int idx = tid; idx < 10 * SXW * (IC / 4); idx += 256) {
        int c4 = idx % (IC / 4);
        int r = idx / (IC / 4);
        int sx = r % SXW, sy = r / SXW;
        int gy = R0 + sy - 1, gx = sx - 1;
        unsigned v = 0;
        if (gy >= 0 && gy < W && gx >= 0 && gx < W)
            v = *(const unsigned*)(xb + ((size_t)gy * W + gx) * IC + c4 * 4);
        unsigned lo = ((v & 0xffu) ? 0x3F80u : 0u) | ((v & 0xff00u) ? 0x3F800000u : 0u);
        unsigned hi = ((v & 0xff0000u) ? 0x3F80u : 0u) | ((v & 0xff000000u) ? 0x3F800000u : 0u);
        *(uint2*)&xs[(sy * SXW + sx) * XP + c4 * 4] = make_uint2(lo, hi);
    }
    __syncthreads();
    uint32_t xsu = (uint32_t)__cvta_generic_to_shared(xs);
    const int l15 = lane & 15, lc8 = (lane >> 4) * 8;
    uint32_t abase[4];
#pragma unroll
    for (int mt = 0; mt < 4; mt++) {
        int p = mg * 64 + mt * 16 + l15;
        int ly = p / W, lx = p % W;
        abase[mt] = xsu + ((ly * SXW + lx) * XP + lc8) * 2;
    }
    float acc[4][4][4];
#pragma unroll
    for (int mt = 0; mt < 4; mt++)
#pragma unroll
        for (int nt = 0; nt < 4; nt++)
#pragma unroll
            for (int i = 0; i < 4; i++) acc[mt][nt][i] = 0.f;
#pragma unroll
    for (int kh = 0; kh < 3; kh++)
#pragma unroll
        for (int kw = 0; kw < 3; kw++)
#pragma unroll
            for (int icb = 0; icb < NICB; icb++) {
                const int it = (kh * 3 + kw) * NICB + icb;
                const int aoff = ((kh * SXW + kw) * XP + icb * 16) * 2;
                uint32_t a[4][4];
#pragma unroll
                for (int mt = 0; mt < 4; mt++) ldm4(a[mt], abase[mt] + aoff);
#pragma unroll
                for (int nt = 0; nt < 4; nt++) {
                    int ntg = ng * 4 + nt;
#pragma unroll
                    for (int sp = 0; sp < 3; sp++) {
                        uint2 b = B[((it * NTG + ntg) * 3 + sp) * 32 + lane];
#pragma unroll
                        for (int mt = 0; mt < 4; mt++)
                            mmab(acc[mt][nt], a[mt][0], a[mt][1], a[mt][2], a[mt][3],
                                 b.x, b.y);
                    }
                }
            }
    float* ui = u + (size_t)z * W * W * OC;
    const int g = lane >> 2, tg = lane & 3;
#pragma unroll
    for (int mt = 0; mt < 4; mt++) {
        int p0 = R0 * W + mg * 64 + mt * 16 + g;
#pragma unroll
        for (int nt = 0; nt < 4; nt++) {
            int oc = ng * 32 + nt * 8 + tg * 2;
            *(float2*)&ui[(size_t)p0 * OC + oc] = make_float2(acc[mt][nt][0], acc[mt][nt][1]);
            *(float2*)&ui[(size_t)(p0 + 8) * OC + oc] = make_float2(acc[mt][nt][2], acc[mt][nt][3]);
        }
    }
}

// ---------------- SF4a GEMM: [400 x 8192](u8) * [8192 -> 512], split-K=4 ----------
__global__ void __launch_bounds__(256)
gemm4a_k(const unsigned char* __restrict__ x, const float* __restrict__ w,
         float* __restrict__ part) {
    __shared__ __align__(16) float xs[16][64];
    __shared__ __align__(16) float ws[16][64];
    const int tid = threadIdx.x;
    const int tm = tid % 16, tn = tid / 16;
    const int bm0 = blockIdx.x * 64, bn0 = blockIdx.y * 64;
    const int k0b = blockIdx.z * 2048;
    unsigned long long acc[4][2];
#pragma unroll
    for (int i = 0; i < 4; i++) { acc[i][0] = 0ULL; acc[i][1] = 0ULL; }
    const int lrow = tid >> 2, lc4 = (tid & 3) * 4;

    for (int k0 = k0b; k0 < k0b + 2048; k0 += 16) {
        int m = bm0 + lrow;
        uchar4 xv = make_uchar4(0, 0, 0, 0);
        if (m < 400) xv = *reinterpret_cast<const uchar4*>(x + (size_t)m * 8192 + k0 + lc4);
        xs[lc4 + 0][lrow] = (float)xv.x; xs[lc4 + 1][lrow] = (float)xv.y;
        xs[lc4 + 2][lrow] = (float)xv.z; xs[lc4 + 3][lrow] = (float)xv.w;
        float4 wv = *reinterpret_cast<const float4*>(w + (size_t)(bn0 + lrow) * 8192 + k0 + lc4);
        ws[lc4 + 0][lrow] = wv.x; ws[lc4 + 1][lrow] = wv.y;
        ws[lc4 + 2][lrow] = wv.z; ws[lc4 + 3][lrow] = wv.w;
        __syncthreads();
#pragma unroll
        for (int kk = 0; kk < 16; kk++) {
            float4 a = *reinterpret_cast<const float4*>(&xs[kk][tm * 4]);
            const unsigned long long* wp =
                reinterpret_cast<const unsigned long long*>(&ws[kk][tn * 4]);
            unsigned long long w0 = wp[0], w1 = wp[1];
            unsigned long long a0 = pk2(a.x, a.x), a1 = pk2(a.y, a.y);
            unsigned long long a2 = pk2(a.z, a.z), a3 = pk2(a.w, a.w);
            acc[0][0] = fma2(a0, w0, acc[0][0]); acc[0][1] = fma2(a0, w1, acc[0][1]);
            acc[1][0] = fma2(a1, w0, acc[1][0]); acc[1][1] = fma2(a1, w1, acc[1][1]);
            acc[2][0] = fma2(a2, w0, acc[2][0]); acc[2][1] = fma2(a2, w1, acc[2][1]);
            acc[3][0] = fma2(a3, w0, acc[3][0]); acc[3][1] = fma2(a3, w1, acc[3][1]);
        }
        __syncthreads();
    }
    float* pb = part + (size_t)blockIdx.z * 204800;
#pragma unroll
    for (int i = 0; i < 4; i++) {
        int m = bm0 + tm * 4 + i;
        if (m < 400) {
            float2 v0 = upk(acc[i][0]), v1 = upk(acc[i][1]);
            float4 v = make_float4(v0.x, v0.y, v1.x, v1.y);
            *reinterpret_cast<float4*>(pb + (size_t)m * 512 + bn0 + tn * 4) = v;
        }
    }
}

__global__ void reduce4_k(const float* __restrict__ part, float* __restrict__ u) {
    int i = blockIdx.x * blockDim.x + threadIdx.x;
    if (i < 204800)
        u[i] = ((part[i] + part[204800 + i]) + part[409600 + i]) + part[614400 + i];
}

// ---------------- SF4b GEMM: [400 x 512](u8) * [512 -> 11] -------------------------
__global__ void gemm4b_k(const unsigned char* __restrict__ x, const float* __restrict__ w,
                         float* __restrict__ u) {
    int tb = blockIdx.x;
    int wid = threadIdx.x >> 5, lid = threadIdx.x & 31;  // 11 warps
    const unsigned char* xr = x + (size_t)tb * 512;
    const float* wr = w + (size_t)wid * 512;
    float s = 0.f;
    for (int k = lid; k < 512; k += 32) s += (float)xr[k] * wr[k];
#pragma unroll
    for (int off = 16; off; off >>= 1) s += __shfl_xor_sync(0xffffffffu, s, off);
    if (lid == 0) u[tb * 11 + wid] = s;
}

// ---------------- final scan: u4b [t][b*11+o] -> d_out [b][11][t] ------------------
__global__ void scan_out_k(const float* __restrict__ u, float* __restrict__ out) {
    int n = threadIdx.x;
    if (n >= 44) return;
    int b = n / 11, o = n % 11;
    float a1 = 0.f, a2 = 0.f, cp = 0.f, r1 = 0.f, r2 = 0.f, sp = 0.f;
    for (int t = 0; t < 100; t++) {
        float c = u[t * 44 + n];
        float uu = C2A * a1 - CA2 * a2 + CB1 * cp;
        float yy = C2A * r1 - CA2 * r2 + CB1 * sp;
        float ss = (uu - 20.0f * yy >= 10.0f) ? 1.0f : 0.0f;
        out[(b * 11 + o) * 100 + t] = ss;
        a2 = a1; a1 = uu; cp = c;
        r2 = r1; r1 = yy; sp = ss;
    }
}

// ---------------- driver ----------------------------------------------------------
extern "C" void kernel_launch(void* const* d_in, const int* in_sizes, int n_in,
                              void* d_out, int out_size) {
    const float* s_in = (const float*)d_in[0];
    const float* w1   = (const float*)d_in[1];
    const float* w2   = (const float*)d_in[2];
    const float* w3   = (const float*)d_in[3];
    const float* wf4a = (const float*)d_in[4];
    const float* wf4b = (const float*)d_in[5];
    float* out = (float*)d_out;

    float *u, *pp, *wp;
    unsigned char *sa, *sb;
    uint2 *b1, *b2, *b3;
    cudaGetSymbolAddress((void**)&u, g_u);
    cudaGetSymbolAddress((void**)&sa, g_s8a);
    cudaGetSymbolAddress((void**)&sb, g_s8b);
    cudaGetSymbolAddress((void**)&pp, g_part);
    cudaGetSymbolAddress((void**)&wp, g_wp);
    cudaGetSymbolAddress((void**)&b1, g_B1);
    cudaGetSymbolAddress((void**)&b2, g_B2);
    cudaGetSymbolAddress((void**)&b3, g_B3);

    // weight prep
    prepB1_k<<<(1920 + 255) / 256, 256>>>(w1, b1);
    prepB3_k<32, 8, 2><<<(13824 + 255) / 256, 256>>>(w2, b2, 13824);
    prepB3_k<64, 16, 4><<<(55296 + 255) / 256, 256>>>(w3, b3, 55296);
    permw_k<<<16384, 256>>>(wf4a, wp);

    // SP0: pool raw input + scan -> sa : [t][b][64][64][2] u8
    scan_in_k<<<128, 256>>>(s_in, sa);
    // SC1: conv 5x5 -> u : [z][64*64][32] f32
    conv1_k<<<dim3(8, 400), 256>>>(sa, b1, u);
    // SC1 scan + SP1 -> sb : [t][b][32][32][32] u8
    scanpool_k<32, 32, 32><<<512, 256>>>(u, sb);
    // SC2: conv 3x3 -> u : [z][32*32][64]
    conv3_k<32, 64, 32, 4, 2><<<dim3(4, 400), 256>>>(sb, b2, u);
    // scan + SP2 -> sa : [t][b][16][16][64] u8
    scanpool_k<64, 16, 16><<<256, 256>>>(u, sa);
    // SC3: conv 3x3 -> u : [z][16*16][128]
    conv3_k<64, 128, 16, 2, 4><<<dim3(2, 400), 256>>>(sa, b3, u);
    // scan + SP3 -> sb : [t][b][8][8][128] u8 == [z][8192]
    scanpool_k<128, 8, 8><<<128, 256>>>(u, sb);
    // SF4a: GEMM split-K + reduce -> u : [z][512]; scan -> sa
    gemm4a_k<<<dim3(7, 8, 4), 256>>>(sb, wp, pp);
    reduce4_k<<<800, 256>>>(pp, u);
    scan_k<<<8, 256>>>(u, sa, 2048);
    // SF4b: GEMM -> u : [z][11]; final scan -> d_out [4][11][100]
    gemm4b_k<<<400, 352>>>(sa, wf4b, u);
    scan_out_k<<<1, 64>>>(u, out);
}

// round 5
// speedup vs baseline: 1.9702x; 1.1099x over previous
#include <cuda_runtime.h>
#include <cuda_bf16.h>
#include <cstdint>

// ---------------- SLAYER constants (double -> f32) --------------------------------
#define C2A 1.8096748360719190f   // 2*exp(-0.1)
#define CA2 0.8187307530779818f   // exp(-0.2)
#define CB1 0.2459603111156949f   // e*exp(-0.1)/10

// ---------------- scratch (static device memory; no allocation) -------------------
#define UMAX 52428800  // 100*4*32*64*64 floats
__device__ float g_u[UMAX];
__device__ unsigned char g_s8a[13107200];
__device__ unsigned char g_s8b[13107200];
__device__ float g_part[8 * 400 * 512];
__device__ uint2 g_B1[5 * 4 * 3 * 32];       // SC1 frag weights
__device__ uint2 g_B2[18 * 8 * 3 * 32];      // SC2 frag weights
__device__ uint2 g_B3[36 * 16 * 3 * 32];     // SC3 frag weights
__device__ uint2 g_B4[512 * 64 * 3 * 32];    // SF4a frag weights (25MB)

// ---------------- mma / ldmatrix helpers ------------------------------------------
__device__ __forceinline__ void mmab(float (&c)[4], uint32_t a0, uint32_t a1,
                                     uint32_t a2, uint32_t a3, uint32_t b0, uint32_t b1) {
    asm volatile(
        "mma.sync.aligned.m16n8k16.row.col.f32.bf16.bf16.f32 "
        "{%0,%1,%2,%3}, {%4,%5,%6,%7}, {%8,%9}, {%0,%1,%2,%3};"
        : "+f"(c[0]), "+f"(c[1]), "+f"(c[2]), "+f"(c[3])
        : "r"(a0), "r"(a1), "r"(a2), "r"(a3), "r"(b0), "r"(b1));
}
__device__ __forceinline__ void ldm4(uint32_t (&a)[4], uint32_t addr) {
    asm volatile("ldmatrix.sync.aligned.m8n8.x4.shared.b16 {%0,%1,%2,%3}, [%4];"
                 : "=r"(a[0]), "=r"(a[1]), "=r"(a[2]), "=r"(a[3]) : "r"(addr));
}

// ---------------- weight 3-way bf16 split -----------------------------------------
__device__ __forceinline__ unsigned short wsplit(float w, int sp) {
    __nv_bfloat16 h = __float2bfloat16(w);
    if (sp == 0) return __bfloat16_as_ushort(h);
    float r = w - __bfloat162float(h);
    __nv_bfloat16 m = __float2bfloat16(r);
    if (sp == 1) return __bfloat16_as_ushort(m);
    float r2 = r - __bfloat162float(m);
    return __bfloat16_as_ushort(__float2bfloat16(r2));
}

// ---------------- prep: SC1 frag weights (k = kw*2+ic, kw>=5 zero) ----------------
__global__ void prepB1_k(const float* __restrict__ wt, uint2* __restrict__ B) {
    int idx = blockIdx.x * blockDim.x + threadIdx.x;
    if (idx >= 5 * 4 * 3 * 32) return;
    int lane = idx & 31;
    int r = idx >> 5;
    int sp = r % 3; r /= 3;
    int nt = r & 3;
    int kh = r >> 2;
    int g = lane >> 2, tg = lane & 3;
    int oc = nt * 8 + g;
    unsigned short v[4];
#pragma unroll
    for (int i = 0; i < 4; i++) {
        int k = tg * 2 + (i & 1) + (i >> 1) * 8;
        int kw = k >> 1, ic = k & 1;
        float w = (kw < 5) ? wt[((oc * 2 + ic) * 5 + kh) * 5 + kw] : 0.f;
        v[i] = wsplit(w, sp);
    }
    B[idx] = make_uint2((unsigned)v[0] | ((unsigned)v[1] << 16),
                        (unsigned)v[2] | ((unsigned)v[3] << 16));
}

// ---------------- prep: 3x3 conv frag weights -------------------------------------
template <int IC, int NTG, int NICB>
__global__ void prepB3_k(const float* __restrict__ wt, uint2* __restrict__ B, int total) {
    int idx = blockIdx.x * blockDim.x + threadIdx.x;
    if (idx >= total) return;
    int lane = idx & 31;
    int r = idx >> 5;
    int sp = r % 3; r /= 3;
    int ntg = r % NTG;
    int it = r / NTG;
    int icb = it % NICB;
    int tap = it / NICB;
    int kh = tap / 3, kw = tap % 3;
    int g = lane >> 2, tg = lane & 3;
    int oc = ntg * 8 + g;
    unsigned short v[4];
#pragma unroll
    for (int i = 0; i < 4; i++) {
        int k = tg * 2 + (i & 1) + (i >> 1) * 8;
        int ic = icb * 16 + k;
        v[i] = wsplit(wt[((oc * IC + ic) * 3 + kh) * 3 + kw], sp);
    }
    B[idx] = make_uint2((unsigned)v[0] | ((unsigned)v[1] << 16),
                        (unsigned)v[2] | ((unsigned)v[3] << 16));
}

// ---------------- prep: SF4a frag weights (one thread -> 4 weights, 3 splits) -----
__global__ void prep4a_k(const float* __restrict__ w, uint2* __restrict__ B) {
    int idx = blockIdx.x * blockDim.x + threadIdx.x;
    if (idx >= 512 * 64 * 32) return;
    int lane = idx & 31;
    int r = idx >> 5;
    int ng = r & 63;
    int kb = r >> 6;
    int g = lane >> 2, tg = lane & 3;
    int n = ng * 8 + g;
    unsigned short v[3][4];
#pragma unroll
    for (int i = 0; i < 4; i++) {
        int k = kb * 16 + tg * 2 + (i & 1) + (i >> 1) * 8;
        float wv = w[(size_t)n * 8192 + k];
        __nv_bfloat16 h = __float2bfloat16(wv);
        float r1 = wv - __bfloat162float(h);
        __nv_bfloat16 m = __float2bfloat16(r1);
        float r2 = r1 - __bfloat162float(m);
        v[0][i] = __bfloat16_as_ushort(h);
        v[1][i] = __bfloat16_as_ushort(m);
        v[2][i] = __bfloat16_as_ushort(__float2bfloat16(r2));
    }
#pragma unroll
    for (int sp = 0; sp < 3; sp++)
        B[((kb * 64 + ng) * 3 + sp) * 32 + lane] =
            make_uint2((unsigned)v[sp][0] | ((unsigned)v[sp][1] << 16),
                       (unsigned)v[sp][2] | ((unsigned)v[sp][3] << 16));
}

// ---------------- SP0: pool(2x2)*11 on raw input + scan -> channel-last u8 --------
__global__ void scan_in_k(const float* __restrict__ sin, unsigned char* __restrict__ sout) {
    const int N = 32768;  // 4 b * 64 * 64 * 2 c
    int n = blockIdx.x * blockDim.x + threadIdx.x;
    if (n >= N) return;
    int c = n & 1, x = (n >> 1) & 63, y = (n >> 7) & 63, b = n >> 13;
    const float* p0 = sin + ((size_t)((b * 2 + c) * 128 + 2 * y) * 128 + 2 * x) * 100;
    const float* p1 = p0 + 100;
    const float* p2 = p0 + 12800;
    const float* p3 = p2 + 100;
    float a1 = 0.f, a2 = 0.f, cp = 0.f, r1 = 0.f, r2 = 0.f, sp = 0.f;
    for (int tc = 0; tc < 100; tc += 4) {
        float4 A = *(const float4*)(p0 + tc);
        float4 Bv = *(const float4*)(p1 + tc);
        float4 Cv = *(const float4*)(p2 + tc);
        float4 D = *(const float4*)(p3 + tc);
        float xs4[4] = {A.x + Bv.x + Cv.x + D.x, A.y + Bv.y + Cv.y + D.y,
                        A.z + Bv.z + Cv.z + D.z, A.w + Bv.w + Cv.w + D.w};
#pragma unroll
        for (int j = 0; j < 4; j++) {
            float xv = 11.0f * xs4[j];
            float uu = C2A * a1 - CA2 * a2 + CB1 * cp;
            float yy = C2A * r1 - CA2 * r2 + CB1 * sp;
            float ss = (uu - 20.0f * yy >= 10.0f) ? 1.0f : 0.0f;
            sout[(size_t)(tc + j) * N + n] = (unsigned char)ss;
            a2 = a1; a1 = uu; cp = xv;
            r2 = r1; r1 = yy; sp = ss;
        }
    }
}

// ---------------- fused conv-scan + pool + pooled-scan (channel-last in) ----------
// u: [z][2h][2w][C] f32 ; out: channel-last or channel-first u8 per CF flag
template <int C, int H, int W, bool CF>
__global__ void scanpool_k(const float* __restrict__ u, unsigned char* __restrict__ s) {
    constexpr int N = 4 * C * H * W;
    int n = blockIdx.x * blockDim.x + threadIdx.x;
    if (n >= N) return;
    int c = n % C;
    int r = n / C;
    int w = r % W, h = (r / W) % H, b = r / (W * H);
    const float* base = u + (size_t)b * 4 * H * W * C + ((size_t)(2 * h) * (2 * W) + 2 * w) * C + c;
    constexpr size_t ZST = (size_t)16 * H * W * C;  // per-t stride (4 images)
    const size_t oidx = CF ? (size_t)(((b * C + c) * H + h) * W + w) : (size_t)n;
    float y1[4], y2[4], xp[4], r1[4], r2[4], sp[4];
#pragma unroll
    for (int i = 0; i < 4; i++) { y1[i] = y2[i] = xp[i] = r1[i] = r2[i] = sp[i] = 0.f; }
    float py1 = 0.f, py2 = 0.f, pxp = 0.f, pr1 = 0.f, pr2 = 0.f, psp = 0.f;
    for (int t = 0; t < 100; t++) {
        float xin[4];
        xin[0] = base[0];
        xin[1] = base[C];
        xin[2] = base[2 * W * C];
        xin[3] = base[(2 * W + 1) * C];
        float ssum = 0.f;
#pragma unroll
        for (int i = 0; i < 4; i++) {
            float yy = C2A * y1[i] - CA2 * y2[i] + CB1 * xp[i];
            float rr = C2A * r1[i] - CA2 * r2[i] + CB1 * sp[i];
            float si = (yy - 20.0f * rr >= 10.0f) ? 1.0f : 0.0f;
            y2[i] = y1[i]; y1[i] = yy; xp[i] = xin[i];
            r2[i] = r1[i]; r1[i] = rr; sp[i] = si;
            ssum += si;
        }
        float pu = C2A * py1 - CA2 * py2 + CB1 * pxp;
        float pr = C2A * pr1 - CA2 * pr2 + CB1 * psp;
        float ps = (pu - 20.0f * pr >= 10.0f) ? 1.0f : 0.0f;
        py2 = py1; py1 = pu; pxp = 11.0f * ssum;
        pr2 = pr1; pr1 = pr; psp = ps;
        s[(size_t)t * N + oidx] = (unsigned char)ps;
        base += ZST;
    }
}

// ---------------- plain psp+spike scan (fp32 u -> u8 spikes) -----------------------
__global__ void scan_k(const float* __restrict__ u, unsigned char* __restrict__ s, int N) {
    int n = blockIdx.x * blockDim.x + threadIdx.x;
    if (n >= N) return;
    float p1 = 0.f, p2 = 0.f, cp = 0.f, r1 = 0.f, r2 = 0.f, sp = 0.f;
    for (int t = 0; t < 100; t++) {
        float c = u[(size_t)t * N + n];
        float uu = C2A * p1 - CA2 * p2 + CB1 * cp;
        float yy = C2A * r1 - CA2 * r2 + CB1 * sp;
        float ss = (uu - 20.0f * yy >= 10.0f) ? 1.0f : 0.0f;
        s[(size_t)t * N + n] = (unsigned char)ss;
        p2 = p1; p1 = uu; cp = c;
        r2 = r1; r1 = yy; sp = ss;
    }
}

// ---------------- SC1: 5x5 conv, IC=2, OC=32, 64x64, tensor-core ------------------
__global__ void __launch_bounds__(256)
conv1_k(const unsigned char* __restrict__ x, const uint2* __restrict__ B,
        float* __restrict__ u) {
    __shared__ __align__(16) __nv_bfloat16 xs[12 * 148];
    const int tid = threadIdx.x, lane = tid & 31, warp = tid >> 5;
    const int z = blockIdx.y, R0 = blockIdx.x * 8;
    const unsigned char* xb = x + (size_t)z * 8192;  // 64*64*2
    for (int idx = tid; idx < 12 * 72; idx += 256) {
        int sy = idx / 72, ix = idx % 72;
        int gy = R0 + sy - 2, gx = ix - 2;
        unsigned v0 = 0, v1 = 0;
        if (gy >= 0 && gy < 64 && gx >= 0 && gx < 64) {
            const unsigned char* p = xb + ((size_t)gy * 64 + gx) * 2;
            v0 = p[0]; v1 = p[1];
        }
        unsigned pack = (v0 ? 0x3F80u : 0u) | (v1 ? 0x3F800000u : 0u);
        *(unsigned*)&xs[sy * 148 + ix * 2] = pack;
    }
    __syncthreads();
    const int g = lane >> 2, tg = lane & 3;
    float acc[4][4][4];
#pragma unroll
    for (int mt = 0; mt < 4; mt++)
#pragma unroll
        for (int nt = 0; nt < 4; nt++)
#pragma unroll
            for (int i = 0; i < 4; i++) acc[mt][nt][i] = 0.f;
    int lyA[4], lxA[4];
#pragma unroll
    for (int mt = 0; mt < 4; mt++) {
        int p = warp * 64 + mt * 16 + g;
        lyA[mt] = p >> 6;
        lxA[mt] = p & 63;
    }
#pragma unroll
    for (int kh = 0; kh < 5; kh++) {
        uint32_t a[4][4];
#pragma unroll
        for (int mt = 0; mt < 4; mt++) {
            int rb = (lyA[mt] + kh) * 148;
            a[mt][0] = *(const unsigned*)&xs[rb + (lxA[mt] + tg) * 2];
            a[mt][1] = *(const unsigned*)&xs[rb + (lxA[mt] + 8 + tg) * 2];
            a[mt][2] = *(const unsigned*)&xs[rb + (lxA[mt] + tg + 4) * 2];
            a[mt][3] = *(const unsigned*)&xs[rb + (lxA[mt] + 8 + tg + 4) * 2];
        }
#pragma unroll
        for (int nt = 0; nt < 4; nt++)
#pragma unroll
            for (int sp = 0; sp < 3; sp++) {
                uint2 b = B[((kh * 4 + nt) * 3 + sp) * 32 + lane];
#pragma unroll
                for (int mt = 0; mt < 4; mt++)
                    mmab(acc[mt][nt], a[mt][0], a[mt][1], a[mt][2], a[mt][3], b.x, b.y);
            }
    }
    float* ui = u + (size_t)z * 4096 * 32;
#pragma unroll
    for (int mt = 0; mt < 4; mt++) {
        int p0 = R0 * 64 + warp * 64 + mt * 16 + g;
#pragma unroll
        for (int nt = 0; nt < 4; nt++) {
            int oc = nt * 8 + tg * 2;
            *(float2*)&ui[(size_t)p0 * 32 + oc] = make_float2(acc[mt][nt][0], acc[mt][nt][1]);
            *(float2*)&ui[(size_t)(p0 + 8) * 32 + oc] = make_float2(acc[mt][nt][2], acc[mt][nt][3]);
        }
    }
}

// ---------------- 3x3 convs (SC2/SC3), tensor-core implicit GEMM ------------------
template <int IC, int OC, int W, int MG, int NG>
__global__ void __launch_bounds__(256)
conv3_k(const unsigned char* __restrict__ x, const uint2* __restrict__ B,
        float* __restrict__ u) {
    constexpr int XP = IC + 8;
    constexpr int SXW = W + 2;
    constexpr int NICB = IC / 16, NTG = OC / 8;
    __shared__ __align__(16) __nv_bfloat16 xs[10 * SXW * XP];
    const int tid = threadIdx.x, lane = tid & 31, warp = tid >> 5;
    const int mg = warp % MG, ng = warp / MG;
    const int z = blockIdx.y, R0 = blockIdx.x * 8;
    const unsigned char* xb = x + (size_t)z * W * W * IC;
    for (int idx = tid; idx < 10 * SXW * (IC / 4); idx += 256) {
        int c4 = idx % (IC / 4);
        int r = idx / (IC / 4);
        int sx = r % SXW, sy = r / SXW;
        int gy = R0 + sy - 1, gx = sx - 1;
        unsigned v = 0;
        if (gy >= 0 && gy < W && gx >= 0 && gx < W)
            v = *(const unsigned*)(xb + ((size_t)gy * W + gx) * IC + c4 * 4);
        unsigned lo = ((v & 0xffu) ? 0x3F80u : 0u) | ((v & 0xff00u) ? 0x3F800000u : 0u);
        unsigned hi = ((v & 0xff0000u) ? 0x3F80u : 0u) | ((v & 0xff000000u) ? 0x3F800000u : 0u);
        *(uint2*)&xs[(sy * SXW + sx) * XP + c4 * 4] = make_uint2(lo, hi);
    }
    __syncthreads();
    uint32_t xsu = (uint32_t)__cvta_generic_to_shared(xs);
    const int l15 = lane & 15, lc8 = (lane >> 4) * 8;
    uint32_t abase[4];
#pragma unroll
    for (int mt = 0; mt < 4; mt++) {
        int p = mg * 64 + mt * 16 + l15;
        int ly = p / W, lx = p % W;
        abase[mt] = xsu + ((ly * SXW + lx) * XP + lc8) * 2;
    }
    float acc[4][4][4];
#pragma unroll
    for (int mt = 0; mt < 4; mt++)
#pragma unroll
        for (int nt = 0; nt < 4; nt++)
#pragma unroll
            for (int i = 0; i < 4; i++) acc[mt][nt][i] = 0.f;
#pragma unroll
    for (int kh = 0; kh < 3; kh++)
#pragma unroll
        for (int kw = 0; kw < 3; kw++)
#pragma unroll
            for (int icb = 0; icb < NICB; icb++) {
                const int it = (kh * 3 + kw) * NICB + icb;
                const int aoff = ((kh * SXW + kw) * XP + icb * 16) * 2;
                uint32_t a[4][4];
#pragma unroll
                for (int mt = 0; mt < 4; mt++) ldm4(a[mt], abase[mt] + aoff);
#pragma unroll
                for (int nt = 0; nt < 4; nt++) {
                    int ntg = ng * 4 + nt;
#pragma unroll
                    for (int sp = 0; sp < 3; sp++) {
                        uint2 b = B[((it * NTG + ntg) * 3 + sp) * 32 + lane];
#pragma unroll
                        for (int mt = 0; mt < 4; mt++)
                            mmab(acc[mt][nt], a[mt][0], a[mt][1], a[mt][2], a[mt][3],
                                 b.x, b.y);
                    }
                }
            }
    float* ui = u + (size_t)z * W * W * OC;
    const int g = lane >> 2, tg = lane & 3;
#pragma unroll
    for (int mt = 0; mt < 4; mt++) {
        int p0 = R0 * W + mg * 64 + mt * 16 + g;
#pragma unroll
        for (int nt = 0; nt < 4; nt++) {
            int oc = ng * 32 + nt * 8 + tg * 2;
            *(float2*)&ui[(size_t)p0 * OC + oc] = make_float2(acc[mt][nt][0], acc[mt][nt][1]);
            *(float2*)&ui[(size_t)(p0 + 8) * OC + oc] = make_float2(acc[mt][nt][2], acc[mt][nt][3]);
        }
    }
}

// ---------------- SF4a tensor-core GEMM: [400x8192](u8) x [8192->512], split-K=8 --
__global__ void __launch_bounds__(256)
gemm4am_k(const unsigned char* __restrict__ x, const uint2* __restrict__ B,
          float* __restrict__ part) {
    constexpr int KP = 72;  // bf16 pitch
    __shared__ __align__(16) __nv_bfloat16 as[128 * KP];
    const int tid = threadIdx.x, lane = tid & 31, warp = tid >> 5;
    const int mg = warp & 1, ng4 = warp >> 1;
    const int M0 = blockIdx.y * 128, N0 = blockIdx.x * 128;
    const int k00 = blockIdx.z * 1024;
    const int l15 = lane & 15, lc8 = (lane >> 4) * 8;
    const int g = lane >> 2, tg = lane & 3;
    uint32_t asu = (uint32_t)__cvta_generic_to_shared(as);
    float acc[4][4][4];
#pragma unroll
    for (int mt = 0; mt < 4; mt++)
#pragma unroll
        for (int nt = 0; nt < 4; nt++)
#pragma unroll
            for (int i = 0; i < 4; i++) acc[mt][nt][i] = 0.f;

    for (int k0 = k00; k0 < k00 + 1024; k0 += 64) {
#pragma unroll
        for (int i = 0; i < 8; i++) {
            int pos = tid + i * 256;
            int row = pos >> 4, c4 = pos & 15;
            uchar4 v = *(const uchar4*)(x + (size_t)(M0 + row) * 8192 + k0 + c4 * 4);
            unsigned lo = (v.x ? 0x3F80u : 0u) | (v.y ? 0x3F800000u : 0u);
            unsigned hi = (v.z ? 0x3F80u : 0u) | (v.w ? 0x3F800000u : 0u);
            *(uint2*)&as[row * KP + c4 * 4] = make_uint2(lo, hi);
        }
        __syncthreads();
#pragma unroll
        for (int kc = 0; kc < 4; kc++) {
            int kb = (k0 >> 4) + kc;
            uint32_t a[4][4];
#pragma unroll
            for (int mt = 0; mt < 4; mt++)
                ldm4(a[mt], asu + (((mg * 64 + mt * 16 + l15) * KP) + lc8 + kc * 16) * 2);
#pragma unroll
            for (int nt = 0; nt < 4; nt++) {
                int ngg = (N0 >> 3) + ng4 * 4 + nt;
#pragma unroll
                for (int sp = 0; sp < 3; sp++) {
                    uint2 b = B[((kb * 64 + ngg) * 3 + sp) * 32 + lane];
#pragma unroll
                    for (int mt = 0; mt < 4; mt++)
                        mmab(acc[mt][nt], a[mt][0], a[mt][1], a[mt][2], a[mt][3], b.x, b.y);
                }
            }
        }
        __syncthreads();
    }
    float* pb = part + (size_t)blockIdx.z * 204800;
#pragma unroll
    for (int mt = 0; mt < 4; mt++) {
        int z0 = M0 + mg * 64 + mt * 16 + g;
#pragma unroll
        for (int nt = 0; nt < 4; nt++) {
            int col = N0 + ng4 * 32 + nt * 8 + tg * 2;
            if (z0 < 400)
                *(float2*)&pb[(size_t)z0 * 512 + col] = make_float2(acc[mt][nt][0], acc[mt][nt][1]);
            if (z0 + 8 < 400)
                *(float2*)&pb[(size_t)(z0 + 8) * 512 + col] = make_float2(acc[mt][nt][2], acc[mt][nt][3]);
        }
    }
}

__global__ void reduce8_k(const float* __restrict__ part, float* __restrict__ u) {
    int i = blockIdx.x * blockDim.x + threadIdx.x;
    if (i >= 204800) return;
    float s = 0.f;
#pragma unroll
    for (int j = 0; j < 8; j++) s += part[(size_t)j * 204800 + i];
    u[i] = s;
}

// ---------------- SF4b GEMM: [400 x 512](u8) * [512 -> 11] -------------------------
__global__ void gemm4b_k(const unsigned char* __restrict__ x, const float* __restrict__ w,
                         float* __restrict__ u) {
    int tb = blockIdx.x;
    int wid = threadIdx.x >> 5, lid = threadIdx.x & 31;  // 11 warps
    const unsigned char* xr = x + (size_t)tb * 512;
    const float* wr = w + (size_t)wid * 512;
    float s = 0.f;
    for (int k = lid; k < 512; k += 32) s += (float)xr[k] * wr[k];
#pragma unroll
    for (int off = 16; off; off >>= 1) s += __shfl_xor_sync(0xffffffffu, s, off);
    if (lid == 0) u[tb * 11 + wid] = s;
}

// ---------------- final scan: u4b [t][b*11+o] -> d_out [b][11][t] ------------------
__global__ void scan_out_k(const float* __restrict__ u, float* __restrict__ out) {
    int n = threadIdx.x;
    if (n >= 44) return;
    int b = n / 11, o = n % 11;
    float a1 = 0.f, a2 = 0.f, cp = 0.f, r1 = 0.f, r2 = 0.f, sp = 0.f;
    for (int t = 0; t < 100; t++) {
        float c = u[t * 44 + n];
        float uu = C2A * a1 - CA2 * a2 + CB1 * cp;
        float yy = C2A * r1 - CA2 * r2 + CB1 * sp;
        float ss = (uu - 20.0f * yy >= 10.0f) ? 1.0f : 0.0f;
        out[(b * 11 + o) * 100 + t] = ss;
        a2 = a1; a1 = uu; cp = c;
        r2 = r1; r1 = yy; sp = ss;
    }
}

// ---------------- driver ----------------------------------------------------------
extern "C" void kernel_launch(void* const* d_in, const int* in_sizes, int n_in,
                              void* d_out, int out_size) {
    const float* s_in = (const float*)d_in[0];
    const float* w1   = (const float*)d_in[1];
    const float* w2   = (const float*)d_in[2];
    const float* w3   = (const float*)d_in[3];
    const float* wf4a = (const float*)d_in[4];
    const float* wf4b = (const float*)d_in[5];
    float* out = (float*)d_out;

    float *u, *pp;
    unsigned char *sa, *sb;
    uint2 *b1, *b2, *b3, *b4;
    cudaGetSymbolAddress((void**)&u, g_u);
    cudaGetSymbolAddress((void**)&sa, g_s8a);
    cudaGetSymbolAddress((void**)&sb, g_s8b);
    cudaGetSymbolAddress((void**)&pp, g_part);
    cudaGetSymbolAddress((void**)&b1, g_B1);
    cudaGetSymbolAddress((void**)&b2, g_B2);
    cudaGetSymbolAddress((void**)&b3, g_B3);
    cudaGetSymbolAddress((void**)&b4, g_B4);

    // weight prep
    prepB1_k<<<(1920 + 255) / 256, 256>>>(w1, b1);
    prepB3_k<32, 8, 2><<<(13824 + 255) / 256, 256>>>(w2, b2, 13824);
    prepB3_k<64, 16, 4><<<(55296 + 255) / 256, 256>>>(w3, b3, 55296);
    prep4a_k<<<4096, 256>>>(wf4a, b4);

    // SP0: pool raw input + scan -> sa : [t][b][64][64][2] u8
    scan_in_k<<<128, 256>>>(s_in, sa);
    // SC1: conv 5x5 -> u : [z][64*64][32] f32
    conv1_k<<<dim3(8, 400), 256>>>(sa, b1, u);
    // SC1 scan + SP1 -> sb : [t][b][32][32][32] u8 (channel-last)
    scanpool_k<32, 32, 32, false><<<512, 256>>>(u, sb);
    // SC2: conv 3x3 -> u : [z][32*32][64]
    conv3_k<32, 64, 32, 4, 2><<<dim3(4, 400), 256>>>(sb, b2, u);
    // scan + SP2 -> sa : [t][b][16][16][64] u8 (channel-last)
    scanpool_k<64, 16, 16, false><<<256, 256>>>(u, sa);
    // SC3: conv 3x3 -> u : [z][16*16][128]
    conv3_k<64, 128, 16, 2, 4><<<dim3(2, 400), 256>>>(sa, b3, u);
    // scan + SP3 -> sb : [t][b][128][8][8] u8 (channel-FIRST = [z][8192] in (c,y,x))
    scanpool_k<128, 8, 8, true><<<128, 256>>>(u, sb);
    // SF4a: tensor-core GEMM split-K=8 + reduce -> u : [z][512]; scan -> sa
    gemm4am_k<<<dim3(4, 4, 8), 256>>>(sb, b4, pp);
    reduce8_k<<<800, 256>>>(pp, u);
    scan_k<<<8, 256>>>(u, sa, 2048);
    // SF4b: GEMM -> u : [z][11]; final scan -> d_out [4][11][100]
    gemm4b_k<<<400, 352>>>(sa, wf4b, u);
    scan_out_k<<<1, 64>>>(u, out);
}

// round 6
// speedup vs baseline: 2.2770x; 1.1557x over previous
#include <cuda_runtime.h>
#include <cuda_fp16.h>
#include <cstdint>

// ---------------- SLAYER constants (double -> f32) --------------------------------
#define C2A 1.8096748360719190f   // 2*exp(-0.1)
#define CA2 0.8187307530779818f   // exp(-0.2)
#define CB1 0.2459603111156949f   // e*exp(-0.1)/10

// ---------------- scratch (static device memory; no allocation) -------------------
#define UMAX 52428800  // 100*4*32*64*64 floats
__device__ float g_u[UMAX];
__device__ unsigned char g_s8a[13107200];
__device__ unsigned char g_s8b[13107200];
__device__ float g_part[8 * 400 * 512];
__device__ uint2 g_B1[5 * 4 * 2 * 32];       // SC1 frag weights (fp16 2-split)
__device__ uint2 g_B2[18 * 8 * 2 * 32];      // SC2 frag weights
__device__ uint2 g_B3[36 * 16 * 2 * 32];     // SC3 frag weights
__device__ uint2 g_B4[512 * 64 * 2 * 32];    // SF4a frag weights

// ---------------- mma / ldmatrix helpers (fp16 in, f32 acc) -----------------------
__device__ __forceinline__ void mmah(float (&c)[4], uint32_t a0, uint32_t a1,
                                     uint32_t a2, uint32_t a3, uint32_t b0, uint32_t b1) {
    asm volatile(
        "mma.sync.aligned.m16n8k16.row.col.f32.f16.f16.f32 "
        "{%0,%1,%2,%3}, {%4,%5,%6,%7}, {%8,%9}, {%0,%1,%2,%3};"
        : "+f"(c[0]), "+f"(c[1]), "+f"(c[2]), "+f"(c[3])
        : "r"(a0), "r"(a1), "r"(a2), "r"(a3), "r"(b0), "r"(b1));
}
__device__ __forceinline__ void ldm4(uint32_t (&a)[4], uint32_t addr) {
    asm volatile("ldmatrix.sync.aligned.m8n8.x4.shared.b16 {%0,%1,%2,%3}, [%4];"
                 : "=r"(a[0]), "=r"(a[1]), "=r"(a[2]), "=r"(a[3]) : "r"(addr));
}

// ---------------- weight 2-way fp16 split (hi + residual, ~22 mantissa bits) ------
__device__ __forceinline__ unsigned short wsplit(float w, int sp) {
    __half h = __float2half_rn(w);
    if (sp == 0) return __half_as_ushort(h);
    float r = w - __half2float(h);
    return __half_as_ushort(__float2half_rn(r));
}

// ---------------- prep: SC1 frag weights (k = kw*2+ic, kw>=5 zero) ----------------
__global__ void prepB1_k(const float* __restrict__ wt, uint2* __restrict__ B) {
    int idx = blockIdx.x * blockDim.x + threadIdx.x;
    if (idx >= 5 * 4 * 2 * 32) return;
    int lane = idx & 31;
    int r = idx >> 5;
    int sp = r % 2; r /= 2;
    int nt = r & 3;
    int kh = r >> 2;
    int g = lane >> 2, tg = lane & 3;
    int oc = nt * 8 + g;
    unsigned short v[4];
#pragma unroll
    for (int i = 0; i < 4; i++) {
        int k = tg * 2 + (i & 1) + (i >> 1) * 8;
        int kw = k >> 1, ic = k & 1;
        float w = (kw < 5) ? wt[((oc * 2 + ic) * 5 + kh) * 5 + kw] : 0.f;
        v[i] = wsplit(w, sp);
    }
    B[idx] = make_uint2((unsigned)v[0] | ((unsigned)v[1] << 16),
                        (unsigned)v[2] | ((unsigned)v[3] << 16));
}

// ---------------- prep: 3x3 conv frag weights -------------------------------------
template <int IC, int NTG, int NICB>
__global__ void prepB3_k(const float* __restrict__ wt, uint2* __restrict__ B, int total) {
    int idx = blockIdx.x * blockDim.x + threadIdx.x;
    if (idx >= total) return;
    int lane = idx & 31;
    int r = idx >> 5;
    int sp = r % 2; r /= 2;
    int ntg = r % NTG;
    int it = r / NTG;
    int icb = it % NICB;
    int tap = it / NICB;
    int kh = tap / 3, kw = tap % 3;
    int g = lane >> 2, tg = lane & 3;
    int oc = ntg * 8 + g;
    unsigned short v[4];
#pragma unroll
    for (int i = 0; i < 4; i++) {
        int k = tg * 2 + (i & 1) + (i >> 1) * 8;
        int ic = icb * 16 + k;
        v[i] = wsplit(wt[((oc * IC + ic) * 3 + kh) * 3 + kw], sp);
    }
    B[idx] = make_uint2((unsigned)v[0] | ((unsigned)v[1] << 16),
                        (unsigned)v[2] | ((unsigned)v[3] << 16));
}

// ---------------- prep: SF4a frag weights -----------------------------------------
__global__ void prep4a_k(const float* __restrict__ w, uint2* __restrict__ B) {
    int idx = blockIdx.x * blockDim.x + threadIdx.x;
    if (idx >= 512 * 64 * 32) return;
    int lane = idx & 31;
    int r = idx >> 5;
    int ng = r & 63;
    int kb = r >> 6;
    int g = lane >> 2, tg = lane & 3;
    int n = ng * 8 + g;
    unsigned short v[2][4];
#pragma unroll
    for (int i = 0; i < 4; i++) {
        int k = kb * 16 + tg * 2 + (i & 1) + (i >> 1) * 8;
        float wv = w[(size_t)n * 8192 + k];
        __half h = __float2half_rn(wv);
        float r1 = wv - __half2float(h);
        v[0][i] = __half_as_ushort(h);
        v[1][i] = __half_as_ushort(__float2half_rn(r1));
    }
#pragma unroll
    for (int sp = 0; sp < 2; sp++)
        B[((kb * 64 + ng) * 2 + sp) * 32 + lane] =
            make_uint2((unsigned)v[sp][0] | ((unsigned)v[sp][1] << 16),
                       (unsigned)v[sp][2] | ((unsigned)v[sp][3] << 16));
}

// ---------------- SP0: pool(2x2)*11 on raw input + scan -> channel-last u8 --------
__global__ void scan_in_k(const float* __restrict__ sin, unsigned char* __restrict__ sout) {
    const int N = 32768;  // 4 b * 64 * 64 * 2 c
    int n = blockIdx.x * blockDim.x + threadIdx.x;
    if (n >= N) return;
    int c = n & 1, x = (n >> 1) & 63, y = (n >> 7) & 63, b = n >> 13;
    const float* p0 = sin + ((size_t)((b * 2 + c) * 128 + 2 * y) * 128 + 2 * x) * 100;
    const float* p1 = p0 + 100;
    const float* p2 = p0 + 12800;
    const float* p3 = p2 + 100;
    float a1 = 0.f, a2 = 0.f, cp = 0.f, r1 = 0.f, r2 = 0.f, sp = 0.f;
    for (int tc = 0; tc < 100; tc += 4) {
        float4 A = *(const float4*)(p0 + tc);
        float4 Bv = *(const float4*)(p1 + tc);
        float4 Cv = *(const float4*)(p2 + tc);
        float4 D = *(const float4*)(p3 + tc);
        float xs4[4] = {A.x + Bv.x + Cv.x + D.x, A.y + Bv.y + Cv.y + D.y,
                        A.z + Bv.z + Cv.z + D.z, A.w + Bv.w + Cv.w + D.w};
#pragma unroll
        for (int j = 0; j < 4; j++) {
            float xv = 11.0f * xs4[j];
            float uu = C2A * a1 - CA2 * a2 + CB1 * cp;
            float yy = C2A * r1 - CA2 * r2 + CB1 * sp;
            float ss = (uu - 20.0f * yy >= 10.0f) ? 1.0f : 0.0f;
            sout[(size_t)(tc + j) * N + n] = (unsigned char)ss;
            a2 = a1; a1 = uu; cp = xv;
            r2 = r1; r1 = yy; sp = ss;
        }
    }
}

// ---------------- fused conv-scan + pool + pooled-scan (channel-last in) ----------
template <int C, int H, int W, bool CF>
__global__ void scanpool_k(const float* __restrict__ u, unsigned char* __restrict__ s) {
    constexpr int N = 4 * C * H * W;
    int n = blockIdx.x * blockDim.x + threadIdx.x;
    if (n >= N) return;
    int c = n % C;
    int r = n / C;
    int w = r % W, h = (r / W) % H, b = r / (W * H);
    const float* base = u + (size_t)b * 4 * H * W * C + ((size_t)(2 * h) * (2 * W) + 2 * w) * C + c;
    constexpr size_t ZST = (size_t)16 * H * W * C;  // per-t stride (4 images)
    const size_t oidx = CF ? (size_t)(((b * C + c) * H + h) * W + w) : (size_t)n;
    float y1[4], y2[4], xp[4], r1[4], r2[4], sp[4];
#pragma unroll
    for (int i = 0; i < 4; i++) { y1[i] = y2[i] = xp[i] = r1[i] = r2[i] = sp[i] = 0.f; }
    float py1 = 0.f, py2 = 0.f, pxp = 0.f, pr1 = 0.f, pr2 = 0.f, psp = 0.f;
    for (int t = 0; t < 100; t++) {
        float xin[4];
        xin[0] = base[0];
        xin[1] = base[C];
        xin[2] = base[2 * W * C];
        xin[3] = base[(2 * W + 1) * C];
        float ssum = 0.f;
#pragma unroll
        for (int i = 0; i < 4; i++) {
            float yy = C2A * y1[i] - CA2 * y2[i] + CB1 * xp[i];
            float rr = C2A * r1[i] - CA2 * r2[i] + CB1 * sp[i];
            float si = (yy - 20.0f * rr >= 10.0f) ? 1.0f : 0.0f;
            y2[i] = y1[i]; y1[i] = yy; xp[i] = xin[i];
            r2[i] = r1[i]; r1[i] = rr; sp[i] = si;
            ssum += si;
        }
        float pu = C2A * py1 - CA2 * py2 + CB1 * pxp;
        float pr = C2A * pr1 - CA2 * pr2 + CB1 * psp;
        float ps = (pu - 20.0f * pr >= 10.0f) ? 1.0f : 0.0f;
        py2 = py1; py1 = pu; pxp = 11.0f * ssum;
        pr2 = pr1; pr1 = pr; psp = ps;
        s[(size_t)t * N + oidx] = (unsigned char)ps;
        base += ZST;
    }
}

// ---------------- SC1: 5x5 conv, IC=2, OC=32, 64x64, tensor-core ------------------
__global__ void __launch_bounds__(256)
conv1_k(const unsigned char* __restrict__ x, const uint2* __restrict__ B,
        float* __restrict__ u) {
    __shared__ __align__(16) __half xs[12 * 148];
    const int tid = threadIdx.x, lane = tid & 31, warp = tid >> 5;
    const int z = blockIdx.y, R0 = blockIdx.x * 8;
    const unsigned char* xb = x + (size_t)z * 8192;  // 64*64*2
    for (int idx = tid; idx < 12 * 72; idx += 256) {
        int sy = idx / 72, ix = idx % 72;
        int gy = R0 + sy - 2, gx = ix - 2;
        unsigned v0 = 0, v1 = 0;
        if (gy >= 0 && gy < 64 && gx >= 0 && gx < 64) {
            const unsigned char* p = xb + ((size_t)gy * 64 + gx) * 2;
            v0 = p[0]; v1 = p[1];
        }
        unsigned pack = (v0 ? 0x3C00u : 0u) | (v1 ? 0x3C000000u : 0u);
        *(unsigned*)&xs[sy * 148 + ix * 2] = pack;
    }
    __syncthreads();
    const int g = lane >> 2, tg = lane & 3;
    float acc[4][4][4];
#pragma unroll
    for (int mt = 0; mt < 4; mt++)
#pragma unroll
        for (int nt = 0; nt < 4; nt++)
#pragma unroll
            for (int i = 0; i < 4; i++) acc[mt][nt][i] = 0.f;
    int lyA[4], lxA[4];
#pragma unroll
    for (int mt = 0; mt < 4; mt++) {
        int p = warp * 64 + mt * 16 + g;
        lyA[mt] = p >> 6;
        lxA[mt] = p & 63;
    }
#pragma unroll
    for (int kh = 0; kh < 5; kh++) {
        uint32_t a[4][4];
#pragma unroll
        for (int mt = 0; mt < 4; mt++) {
            int rb = (lyA[mt] + kh) * 148;
            a[mt][0] = *(const unsigned*)&xs[rb + (lxA[mt] + tg) * 2];
            a[mt][1] = *(const unsigned*)&xs[rb + (lxA[mt] + 8 + tg) * 2];
            a[mt][2] = *(const unsigned*)&xs[rb + (lxA[mt] + tg + 4) * 2];
            a[mt][3] = *(const unsigned*)&xs[rb + (lxA[mt] + 8 + tg + 4) * 2];
        }
#pragma unroll
        for (int nt = 0; nt < 4; nt++)
#pragma unroll
            for (int sp = 0; sp < 2; sp++) {
                uint2 b = B[((kh * 4 + nt) * 2 + sp) * 32 + lane];
#pragma unroll
                for (int mt = 0; mt < 4; mt++)
                    mmah(acc[mt][nt], a[mt][0], a[mt][1], a[mt][2], a[mt][3], b.x, b.y);
            }
    }
    float* ui = u + (size_t)z * 4096 * 32;
#pragma unroll
    for (int mt = 0; mt < 4; mt++) {
        int p0 = R0 * 64 + warp * 64 + mt * 16 + g;
#pragma unroll
        for (int nt = 0; nt < 4; nt++) {
            int oc = nt * 8 + tg * 2;
            *(float2*)&ui[(size_t)p0 * 32 + oc] = make_float2(acc[mt][nt][0], acc[mt][nt][1]);
            *(float2*)&ui[(size_t)(p0 + 8) * 32 + oc] = make_float2(acc[mt][nt][2], acc[mt][nt][3]);
        }
    }
}

// ---------------- 3x3 convs (SC2/SC3), tensor-core implicit GEMM ------------------
template <int IC, int OC, int W, int MG, int NG>
__global__ void __launch_bounds__(256)
conv3_k(const unsigned char* __restrict__ x, const uint2* __restrict__ B,
        float* __restrict__ u) {
    constexpr int XP = IC + 8;
    constexpr int SXW = W + 2;
    constexpr int NICB = IC / 16, NTG = OC / 8;
    __shared__ __align__(16) __half xs[10 * SXW * XP];
    const int tid = threadIdx.x, lane = tid & 31, warp = tid >> 5;
    const int mg = warp % MG, ng = warp / MG;
    const int z = blockIdx.y, R0 = blockIdx.x * 8;
    const unsigned char* xb = x + (size_t)z * W * W * IC;
    for (int idx = tid; idx < 10 * SXW * (IC / 4); idx += 256) {
        int c4 = idx % (IC / 4);
        int r = idx / (IC / 4);
        int sx = r % SXW, sy = r / SXW;
        int gy = R0 + sy - 1, gx = sx - 1;
        unsigned v = 0;
        if (gy >= 0 && gy < W && gx >= 0 && gx < W)
            v = *(const unsigned*)(xb + ((size_t)gy * W + gx) * IC + c4 * 4);
        unsigned lo = ((v & 0xffu) ? 0x3C00u : 0u) | ((v & 0xff00u) ? 0x3C000000u : 0u);
        unsigned hi = ((v & 0xff0000u) ? 0x3C00u : 0u) | ((v & 0xff000000u) ? 0x3C000000u : 0u);
        *(uint2*)&xs[(sy * SXW + sx) * XP + c4 * 4] = make_uint2(lo, hi);
    }
    __syncthreads();
    uint32_t xsu = (uint32_t)__cvta_generic_to_shared(xs);
    const int l15 = lane & 15, lc8 = (lane >> 4) * 8;
    uint32_t abase[4];
#pragma unroll
    for (int mt = 0; mt < 4; mt++) {
        int p = mg * 64 + mt * 16 + l15;
        int ly = p / W, lx = p % W;
        abase[mt] = xsu + ((ly * SXW + lx) * XP + lc8) * 2;
    }
    float acc[4][4][4];
#pragma unroll
    for (int mt = 0; mt < 4; mt++)
#pragma unroll
        for (int nt = 0; nt < 4; nt++)
#pragma unroll
            for (int i = 0; i < 4; i++) acc[mt][nt][i] = 0.f;
#pragma unroll
    for (int kh = 0; kh < 3; kh++)
#pragma unroll
        for (int kw = 0; kw < 3; kw++)
#pragma unroll
            for (int icb = 0; icb < NICB; icb++) {
                const int it = (kh * 3 + kw) * NICB + icb;
                const int aoff = ((kh * SXW + kw) * XP + icb * 16) * 2;
                uint32_t a[4][4];
#pragma unroll
                for (int mt = 0; mt < 4; mt++) ldm4(a[mt], abase[mt] + aoff);
#pragma unroll
                for (int nt = 0; nt < 4; nt++) {
                    int ntg = ng * 4 + nt;
#pragma unroll
                    for (int sp = 0; sp < 2; sp++) {
                        uint2 b = B[((it * NTG + ntg) * 2 + sp) * 32 + lane];
#pragma unroll
                        for (int mt = 0; mt < 4; mt++)
                            mmah(acc[mt][nt], a[mt][0], a[mt][1], a[mt][2], a[mt][3],
                                 b.x, b.y);
                    }
                }
            }
    float* ui = u + (size_t)z * W * W * OC;
    const int g = lane >> 2, tg = lane & 3;
#pragma unroll
    for (int mt = 0; mt < 4; mt++) {
        int p0 = R0 * W + mg * 64 + mt * 16 + g;
#pragma unroll
        for (int nt = 0; nt < 4; nt++) {
            int oc = ng * 32 + nt * 8 + tg * 2;
            *(float2*)&ui[(size_t)p0 * OC + oc] = make_float2(acc[mt][nt][0], acc[mt][nt][1]);
            *(float2*)&ui[(size_t)(p0 + 8) * OC + oc] = make_float2(acc[mt][nt][2], acc[mt][nt][3]);
        }
    }
}

// ---------------- SF4a tensor-core GEMM: [400x8192](u8) x [8192->512], split-K=8 --
__global__ void __launch_bounds__(256)
gemm4am_k(const unsigned char* __restrict__ x, const uint2* __restrict__ B,
          float* __restrict__ part) {
    constexpr int KP = 72;  // fp16 pitch
    __shared__ __align__(16) __half as[128 * KP];
    const int tid = threadIdx.x, lane = tid & 31, warp = tid >> 5;
    const int mg = warp & 1, ng4 = warp >> 1;
    const int M0 = blockIdx.y * 128, N0 = blockIdx.x * 128;
    const int k00 = blockIdx.z * 1024;
    const int l15 = lane & 15, lc8 = (lane >> 4) * 8;
    const int g = lane >> 2, tg = lane & 3;
    uint32_t asu = (uint32_t)__cvta_generic_to_shared(as);
    float acc[4][4][4];
#pragma unroll
    for (int mt = 0; mt < 4; mt++)
#pragma unroll
        for (int nt = 0; nt < 4; nt++)
#pragma unroll
            for (int i = 0; i < 4; i++) acc[mt][nt][i] = 0.f;

    for (int k0 = k00; k0 < k00 + 1024; k0 += 64) {
#pragma unroll
        for (int i = 0; i < 8; i++) {
            int pos = tid + i * 256;
            int row = pos >> 4, c4 = pos & 15;
            uchar4 v = *(const uchar4*)(x + (size_t)(M0 + row) * 8192 + k0 + c4 * 4);
            unsigned lo = (v.x ? 0x3C00u : 0u) | (v.y ? 0x3C000000u : 0u);
            unsigned hi = (v.z ? 0x3C00u : 0u) | (v.w ? 0x3C000000u : 0u);
            *(uint2*)&as[row * KP + c4 * 4] = make_uint2(lo, hi);
        }
        __syncthreads();
#pragma unroll
        for (int kc = 0; kc < 4; kc++) {
            int kb = (k0 >> 4) + kc;
            uint32_t a[4][4];
#pragma unroll
            for (int mt = 0; mt < 4; mt++)
                ldm4(a[mt], asu + (((mg * 64 + mt * 16 + l15) * KP) + lc8 + kc * 16) * 2);
#pragma unroll
            for (int nt = 0; nt < 4; nt++) {
                int ngg = (N0 >> 3) + ng4 * 4 + nt;
#pragma unroll
                for (int sp = 0; sp < 2; sp++) {
                    uint2 b = B[((kb * 64 + ngg) * 2 + sp) * 32 + lane];
#pragma unroll
                    for (int mt = 0; mt < 4; mt++)
                        mmah(acc[mt][nt], a[mt][0], a[mt][1], a[mt][2], a[mt][3], b.x, b.y);
                }
            }
        }
        __syncthreads();
    }
    float* pb = part + (size_t)blockIdx.z * 204800;
#pragma unroll
    for (int mt = 0; mt < 4; mt++) {
        int z0 = M0 + mg * 64 + mt * 16 + g;
#pragma unroll
        for (int nt = 0; nt < 4; nt++) {
            int col = N0 + ng4 * 32 + nt * 8 + tg * 2;
            if (z0 < 400)
                *(float2*)&pb[(size_t)z0 * 512 + col] = make_float2(acc[mt][nt][0], acc[mt][nt][1]);
            if (z0 + 8 < 400)
                *(float2*)&pb[(size_t)(z0 + 8) * 512 + col] = make_float2(acc[mt][nt][2], acc[mt][nt][3]);
        }
    }
}

// ---------------- SF4a scan: sums 8 split-K partials inside the IIR ----------------
__global__ void scan4a_k(const float* __restrict__ part, unsigned char* __restrict__ s) {
    int n = blockIdx.x * blockDim.x + threadIdx.x;
    if (n >= 2048) return;
    float p1 = 0.f, p2 = 0.f, cp = 0.f, r1 = 0.f, r2 = 0.f, sp = 0.f;
    for (int t = 0; t < 100; t++) {
        float c = 0.f;
#pragma unroll
        for (int j = 0; j < 8; j++) c += part[(size_t)j * 204800 + t * 2048 + n];
        float uu = C2A * p1 - CA2 * p2 + CB1 * cp;
        float yy = C2A * r1 - CA2 * r2 + CB1 * sp;
        float ss = (uu - 20.0f * yy >= 10.0f) ? 1.0f : 0.0f;
        s[(size_t)t * 2048 + n] = (unsigned char)ss;
        p2 = p1; p1 = uu; cp = c;
        r2 = r1; r1 = yy; sp = ss;
    }
}

// ---------------- SF4b GEMM: [400 x 512](u8) * [512 -> 11] -------------------------
__global__ void gemm4b_k(const unsigned char* __restrict__ x, const float* __restrict__ w,
                         float* __restrict__ u) {
    int tb = blockIdx.x;
    int wid = threadIdx.x >> 5, lid = threadIdx.x & 31;  // 11 warps
    const unsigned char* xr = x + (size_t)tb * 512;
    const float* wr = w + (size_t)wid * 512;
    float s = 0.f;
    for (int k = lid; k < 512; k += 32) s += (float)xr[k] * wr[k];
#pragma unroll
    for (int off = 16; off; off >>= 1) s += __shfl_xor_sync(0xffffffffu, s, off);
    if (lid == 0) u[tb * 11 + wid] = s;
}

// ---------------- final scan: u4b [t][b*11+o] -> d_out [b][11][t] ------------------
__global__ void scan_out_k(const float* __restrict__ u, float* __restrict__ out) {
    int n = threadIdx.x;
    if (n >= 44) return;
    int b = n / 11, o = n % 11;
    float a1 = 0.f, a2 = 0.f, cp = 0.f, r1 = 0.f, r2 = 0.f, sp = 0.f;
    for (int t = 0; t < 100; t++) {
        float c = u[t * 44 + n];
        float uu = C2A * a1 - CA2 * a2 + CB1 * cp;
        float yy = C2A * r1 - CA2 * r2 + CB1 * sp;
        float ss = (uu - 20.0f * yy >= 10.0f) ? 1.0f : 0.0f;
        out[(b * 11 + o) * 100 + t] = ss;
        a2 = a1; a1 = uu; cp = c;
        r2 = r1; r1 = yy; sp = ss;
    }
}

// ---------------- driver ----------------------------------------------------------
extern "C" void kernel_launch(void* const* d_in, const int* in_sizes, int n_in,
                              void* d_out, int out_size) {
    const float* s_in = (const float*)d_in[0];
    const float* w1   = (const float*)d_in[1];
    const float* w2   = (const float*)d_in[2];
    const float* w3   = (const float*)d_in[3];
    const float* wf4a = (const float*)d_in[4];
    const float* wf4b = (const float*)d_in[5];
    float* out = (float*)d_out;

    float *u, *pp;
    unsigned char *sa, *sb;
    uint2 *b1, *b2, *b3, *b4;
    cudaGetSymbolAddress((void**)&u, g_u);
    cudaGetSymbolAddress((void**)&sa, g_s8a);
    cudaGetSymbolAddress((void**)&sb, g_s8b);
    cudaGetSymbolAddress((void**)&pp, g_part);
    cudaGetSymbolAddress((void**)&b1, g_B1);
    cudaGetSymbolAddress((void**)&b2, g_B2);
    cudaGetSymbolAddress((void**)&b3, g_B3);
    cudaGetSymbolAddress((void**)&b4, g_B4);

    // weight prep (fp16 2-split)
    prepB1_k<<<(1280 + 255) / 256, 256>>>(w1, b1);
    prepB3_k<32, 8, 2><<<(9216 + 255) / 256, 256>>>(w2, b2, 9216);
    prepB3_k<64, 16, 4><<<(36864 + 255) / 256, 256>>>(w3, b3, 36864);
    prep4a_k<<<4096, 256>>>(wf4a, b4);

    // SP0: pool raw input + scan -> sa : [t][b][64][64][2] u8
    scan_in_k<<<128, 256>>>(s_in, sa);
    // SC1: conv 5x5 -> u : [z][64*64][32] f32
    conv1_k<<<dim3(8, 400), 256>>>(sa, b1, u);
    // SC1 scan + SP1 -> sb : [t][b][32][32][32] u8 (channel-last)
    scanpool_k<32, 32, 32, false><<<512, 256>>>(u, sb);
    // SC2: conv 3x3 -> u : [z][32*32][64]
    conv3_k<32, 64, 32, 4, 2><<<dim3(4, 400), 256>>>(sb, b2, u);
    // scan + SP2 -> sa : [t][b][16][16][64] u8 (channel-last)
    scanpool_k<64, 16, 16, false><<<256, 256>>>(u, sa);
    // SC3: conv 3x3 -> u : [z][16*16][128]
    conv3_k<64, 128, 16, 2, 4><<<dim3(2, 400), 256>>>(sa, b3, u);
    // scan + SP3 -> sb : [t][b][128][8][8] u8 (channel-FIRST = [z][8192] in (c,y,x))
    scanpool_k<128, 8, 8, true><<<128, 256>>>(u, sb);
    // SF4a: tensor-core GEMM split-K=8 -> part; fused reduce+scan -> sa
    gemm4am_k<<<dim3(4, 4, 8), 256>>>(sb, b4, pp);
    scan4a_k<<<8, 256>>>(pp, sa);
    // SF4b: GEMM -> u : [z][11]; final scan -> d_out [4][11][100]
    gemm4b_k<<<400, 352>>>(sa, wf4b, u);
    scan_out_k<<<1, 64>>>(u, out);
}